// round 5
// baseline (speedup 1.0000x reference)
#include <cuda_runtime.h>
#include <cuda_bf16.h>
#include <cstdint>

#define NN 50000
#define EE 800000
#define RR 5
#define DD 128
#define NTILE 391                 // ceil(50000/128)
#define NBKT (NN * RR)
#define SCAN_T 256
#define SCAN_ELT 8
#define SCAN_BLOCK (SCAN_T * SCAN_ELT)
#define NSCB ((NBKT + SCAN_BLOCK - 1) / SCAN_BLOCK)

// ---------------- device scratch ----------------
__device__ float g_x[NN * DD];
__device__ float g_y[NN * DD];
__device__ int   g_bcnt[NBKT];
__device__ float g_inv[NBKT];
__device__ int   g_rp[NBKT + 1];
__device__ int   g_wpos[NBKT];
__device__ int   g_aux[256];
__device__ int   g_eidx[EE];

// fragment-ordered A operand: [tile][chunk 6][8192 words], hi & lo
__device__ uint32_t g_Afh[(size_t)NTILE * 6 * 8192];
__device__ uint32_t g_Afl[(size_t)NTILE * 6 * 8192];

// encoder B ([n][K] bf16 hi/lo)
#define OFF_DES 0
#define OFF_TW  (32 * 768)
__device__ __nv_bfloat16 g_Bh[2 * 32 * 768];
__device__ __nv_bfloat16 g_Bl[2 * 32 * 768];
// fragment-ordered B: layer(6 chunks) + W_in(1) + W_o1(1), 8192 words per chunk
#define FOFF_LAYER 0
#define FOFF_IN    49152
#define FOFF_O1    57344
__device__ uint32_t g_Bfh[65536];
__device__ uint32_t g_Bfl[65536];

__device__ __forceinline__ float lrelu(float v) { return v > 0.f ? v : 0.01f * v; }

__device__ __forceinline__ void mma16816(float* d, const uint32_t* a, const uint32_t* b) {
    asm volatile(
        "mma.sync.aligned.m16n8k16.row.col.f32.bf16.bf16.f32 "
        "{%0,%1,%2,%3}, {%4,%5,%6,%7}, {%8,%9}, {%0,%1,%2,%3};"
        : "+f"(d[0]), "+f"(d[1]), "+f"(d[2]), "+f"(d[3])
        : "r"(a[0]), "r"(a[1]), "r"(a[2]), "r"(a[3]), "r"(b[0]), "r"(b[1]));
}
__device__ __forceinline__ uint32_t smem_u32(const void* p) {
    uint32_t a;
    asm("{ .reg .u64 t; cvta.to.shared.u64 t, %1; cvt.u32.u64 %0, t; }" : "=r"(a) : "l"(p));
    return a;
}
__device__ __forceinline__ void cp16(uint32_t saddr, const void* g) {
    asm volatile("cp.async.cg.shared.global [%0], [%1], 16;" :: "r"(saddr), "l"(g));
}
// split-bf16 convert + store float4 (row, c4) into fragment-ordered smem (h at sh[0..], l at sh[8192..])
__device__ __forceinline__ void frag_store(uint32_t* sh, int row, int c4, float4 v) {
    __nv_bfloat16 h0 = __float2bfloat16_rn(v.x), h1 = __float2bfloat16_rn(v.y);
    __nv_bfloat16 h2 = __float2bfloat16_rn(v.z), h3 = __float2bfloat16_rn(v.w);
    __nv_bfloat162 H01(h0, h1), H23(h2, h3);
    __nv_bfloat162 L01 = __floats2bfloat162_rn(v.x - __bfloat162float(h0), v.y - __bfloat162float(h1));
    __nv_bfloat162 L23 = __floats2bfloat162_rn(v.z - __bfloat162float(h2), v.w - __bfloat162float(h3));
    int mb = row >> 4, rm = row & 15, g = rm & 7, r1 = rm >> 3;
    int ks = c4 >> 4, khalf = (c4 >> 3) & 1, t0 = (c4 >> 1) & 3;
    int base = ((mb * 8 + ks) * 32 + g * 4 + t0) * 4 + (r1 + 2 * khalf);
    sh[base] = *reinterpret_cast<uint32_t*>(&H01);
    sh[base + 4] = *reinterpret_cast<uint32_t*>(&H23);
    sh[8192 + base] = *reinterpret_cast<uint32_t*>(&L01);
    sh[8192 + base + 4] = *reinterpret_cast<uint32_t*>(&L23);
}

// ---------------- small kernels ----------------
__global__ void k_zero_int(int* __restrict__ p, int n) {
    int i = blockIdx.x * blockDim.x + threadIdx.x;
    if (i < n) p[i] = 0;
}
__global__ void k_count(const int* __restrict__ ei, const int* __restrict__ et) {
    int e = blockIdx.x * blockDim.x + threadIdx.x;
    if (e < EE) atomicAdd(&g_bcnt[ei[EE + e] * RR + et[e]], 1);
}
__global__ void k_invert() {
    int i = blockIdx.x * blockDim.x + threadIdx.x;
    if (i < NBKT) g_inv[i] = 1.f / (float)max(g_bcnt[i], 1);
}
__global__ void k_scan1() {
    __shared__ int sh[SCAN_T];
    int b = blockIdx.x, t = threadIdx.x;
    int base = b * SCAN_BLOCK + t * SCAN_ELT;
    int v[SCAN_ELT], sum = 0;
#pragma unroll
    for (int i = 0; i < SCAN_ELT; i++) {
        v[i] = (base + i < NBKT) ? g_bcnt[base + i] : 0;
        sum += v[i];
    }
    sh[t] = sum;
    __syncthreads();
    for (int off = 1; off < SCAN_T; off <<= 1) {
        int x = (t >= off) ? sh[t - off] : 0;
        __syncthreads();
        sh[t] += x;
        __syncthreads();
    }
    int excl = sh[t] - sum;
#pragma unroll
    for (int i = 0; i < SCAN_ELT; i++) {
        if (base + i < NBKT) g_rp[base + i] = excl;
        excl += v[i];
    }
    if (t == SCAN_T - 1) g_aux[b] = sh[t];
}
__global__ void k_scan2() {
    __shared__ int sh[256];
    int t = threadIdx.x;
    int v = (t < NSCB) ? g_aux[t] : 0;
    sh[t] = v;
    __syncthreads();
    for (int off = 1; off < 256; off <<= 1) {
        int x = (t >= off) ? sh[t - off] : 0;
        __syncthreads();
        sh[t] += x;
        __syncthreads();
    }
    g_aux[t] = sh[t] - v;
}
__global__ void k_scan3() {
    int i = blockIdx.x * blockDim.x + threadIdx.x;
    if (i < NBKT) {
        int v = g_rp[i] + g_aux[i / SCAN_BLOCK];
        g_rp[i] = v;
        g_wpos[i] = v;
    }
    if (i == 0) g_rp[NBKT] = EE;
}
__global__ void k_fill(const int* __restrict__ ei, const int* __restrict__ et) {
    int e = blockIdx.x * blockDim.x + threadIdx.x;
    if (e >= EE) return;
    int b = ei[EE + e] * RR + et[e];
    int pos = atomicAdd(&g_wpos[b], 1);
    g_eidx[pos] = ei[e];
}

// split+transpose B for encoders: src [K][Nc] -> [Nc][K] hi/lo bf16
__global__ void k_prep(const float* __restrict__ B0, int K, int Nc,
                       __nv_bfloat16* __restrict__ Bh, __nv_bfloat16* __restrict__ Bl) {
    int i = blockIdx.x * blockDim.x + threadIdx.x;
    if (i >= Nc * K) return;
    int n = i / K, k = i % K;
    float v = B0[(size_t)k * Nc + n];
    __nv_bfloat16 h = __float2bfloat16_rn(v);
    Bh[(size_t)n * K + k] = h;
    Bl[(size_t)n * K + k] = __float2bfloat16_rn(v - __bfloat162float(h));
}
// fragment-ordered B prep: chunk c<nch-1 from rel (per-relation [128][128]), last chunk from root.
__global__ void k_prep_fragB(const float* __restrict__ rel, const float* __restrict__ root, int nch,
                             uint32_t* __restrict__ oh, uint32_t* __restrict__ ol) {
    int i = blockIdx.x * blockDim.x + threadIdx.x;
    if (i >= nch * 8192) return;
    int c = i >> 13, w = i & 8191;
    int nb = w >> 9, ks = (w >> 6) & 7, lane = (w >> 1) & 31, rr = w & 1;
    int g = lane >> 2, t = lane & 3;
    int n = nb * 8 + g;
    int kl = ks * 16 + rr * 8 + t * 2;
    const float* src = (c == nch - 1) ? root : (rel + (size_t)c * 16384);
    float v0 = src[kl * 128 + n];
    float v1 = src[(kl + 1) * 128 + n];
    __nv_bfloat16 h0 = __float2bfloat16_rn(v0), h1 = __float2bfloat16_rn(v1);
    __nv_bfloat162 H(h0, h1);
    __nv_bfloat162 L = __floats2bfloat162_rn(v0 - __bfloat162float(h0), v1 - __bfloat162float(h1));
    oh[i] = *reinterpret_cast<uint32_t*>(&H);
    ol[i] = *reinterpret_cast<uint32_t*>(&L);
}

__global__ void k_enc_small(const float* __restrict__ np_, const float* __restrict__ cp,
                            const float* __restrict__ Wnp, const float* __restrict__ bnp,
                            const float* __restrict__ Wcp, const float* __restrict__ bcp,
                            float* __restrict__ q) {
    int i = blockIdx.x * blockDim.x + threadIdx.x;
    if (i >= NN * 64) return;
    int n = i >> 6, c = i & 63;
    float s; int col;
    if (c < 32) {
        s = bnp[c];
#pragma unroll
        for (int k = 0; k < 6; k++) s += np_[n * 6 + k] * Wnp[k * 32 + c];
        col = 64 + c;
    } else {
        int cc = c - 32;
        s = bcp[cc];
#pragma unroll
        for (int k = 0; k < 11; k++) s += cp[n * 11 + k] * Wcp[k * 32 + cc];
        col = 96 + cc;
    }
    q[n * DD + col] = lrelu(s);
}

__global__ void k_head(const float* __restrict__ z, const float* __restrict__ W,
                       const float* __restrict__ b, float* __restrict__ out) {
    int gt = blockIdx.x * blockDim.x + threadIdx.x;
    int warp = gt >> 5, lane = gt & 31;
    if (warp >= NN) return;
    float4 v = *reinterpret_cast<const float4*>(&z[(size_t)warp * DD + lane * 4]);
    float arr[4] = {v.x, v.y, v.z, v.w};
    float s0 = 0.f, s1 = 0.f;
#pragma unroll
    for (int t = 0; t < 4; t++) {
        s0 += arr[t] * W[(lane * 4 + t) * 2 + 0];
        s1 += arr[t] * W[(lane * 4 + t) * 2 + 1];
    }
#pragma unroll
    for (int o = 16; o > 0; o >>= 1) {
        s0 += __shfl_xor_sync(0xffffffffu, s0, o);
        s1 += __shfl_xor_sync(0xffffffffu, s1, o);
    }
    if (lane == 0) { out[warp * 2 + 0] = s0 + b[0]; out[warp * 2 + 1] = s1 + b[1]; }
}

// ---------------- aggregate-first: build A-operand fragments ----------------
// blockIdx = (tile, chunk). chunk<5: A[row,:] = inv * sum_{src in bucket(dst,chunk)} x[src,:]
// chunk==5: A[row,:] = x[dst,:]
__global__ __launch_bounds__(256) void k_aggX(const float* __restrict__ x,
                                              uint32_t* __restrict__ gh, uint32_t* __restrict__ gl) {
    extern __shared__ uint32_t sh[];  // h [0,8192), l [8192,16384)
    const int tid = threadIdx.x, lane = tid & 31, wid = tid >> 5;
    const int tile = blockIdx.x, r = blockIdx.y;
    const int n0 = tile * 128;
    if (r < 5) {
        const int c4 = lane * 4;
#pragma unroll 1
        for (int i = 0; i < 16; i++) {
            int row = wid * 16 + i;
            int dst = n0 + row;
            float4 v = make_float4(0.f, 0.f, 0.f, 0.f);
            if (dst < NN) {
                int b = dst * RR + r;
                int s0 = g_rp[b], e0 = g_rp[b + 1];
                float sc = g_inv[b];
                float4 p0 = make_float4(0.f, 0.f, 0.f, 0.f);
                float4 p1 = make_float4(0.f, 0.f, 0.f, 0.f);
                int j = s0;
                for (; j + 2 <= e0; j += 2) {
                    int sa = g_eidx[j], sb = g_eidx[j + 1];
                    float4 a = *reinterpret_cast<const float4*>(&x[(size_t)sa * DD + c4]);
                    float4 bb = *reinterpret_cast<const float4*>(&x[(size_t)sb * DD + c4]);
                    p0.x += a.x; p0.y += a.y; p0.z += a.z; p0.w += a.w;
                    p1.x += bb.x; p1.y += bb.y; p1.z += bb.z; p1.w += bb.w;
                }
                if (j < e0) {
                    float4 a = *reinterpret_cast<const float4*>(&x[(size_t)g_eidx[j] * DD + c4]);
                    p0.x += a.x; p0.y += a.y; p0.z += a.z; p0.w += a.w;
                }
                v.x = (p0.x + p1.x) * sc;
                v.y = (p0.y + p1.y) * sc;
                v.z = (p0.z + p1.z) * sc;
                v.w = (p0.w + p1.w) * sc;
            }
            frag_store(sh, row, c4, v);
        }
    } else {
#pragma unroll 1
        for (int it = 0; it < 16; it++) {
            int idx = it * 256 + tid;
            int row = idx >> 5, c4 = (idx & 31) * 4;
            int dst = n0 + row;
            float4 v = make_float4(0.f, 0.f, 0.f, 0.f);
            if (dst < NN) v = *reinterpret_cast<const float4*>(&x[(size_t)dst * DD + c4]);
            frag_store(sh, row, c4, v);
        }
    }
    __syncthreads();
    size_t base = ((size_t)tile * 6 + r) * 8192;
#pragma unroll
    for (int i = 0; i < 8; i++) {
        int w = (i * 256 + tid) * 4;
        *reinterpret_cast<uint4*>(&gh[base + w]) = *reinterpret_cast<const uint4*>(&sh[w]);
        *reinterpret_cast<uint4*>(&gl[base + w]) = *reinterpret_cast<const uint4*>(&sh[8192 + w]);
    }
}

// ---------------- layer GEMM: [128,768]@[768,128], all operands cp.async fragments ----------------
__global__ __launch_bounds__(256) void k_lgemm(const uint32_t* __restrict__ Afh, const uint32_t* __restrict__ Afl,
                                               const uint32_t* __restrict__ Bfh, const uint32_t* __restrict__ Bfl,
                                               const float* __restrict__ bias, float* __restrict__ Cout) {
    extern __shared__ uint32_t sm[];
    // A stage s: s*16384 words (h 8192, l 8192). Bh buf: 32768. Bl buf: 40960. Total 49152 words.
    const int tid = threadIdx.x, lane = tid & 31, wid = tid >> 5;
    const int wm = wid >> 2, wn = wid & 3;
    const int tile = blockIdx.x;
    const int n0 = tile * 128;
    const uint32_t smb = smem_u32(sm);
    const size_t abase = (size_t)tile * 6 * 8192;

    float acc[4][4][4];
#pragma unroll
    for (int i = 0; i < 4; i++)
#pragma unroll
        for (int j = 0; j < 4; j++)
#pragma unroll
            for (int q = 0; q < 4; q++) acc[i][j][q] = 0.f;

#define PF_A(C) do { \
    uint32_t dst_ = smb + ((((C) & 1) * 16384u) << 2); \
    const uint32_t* sh_ = Afh + abase + (size_t)(C) * 8192; \
    const uint32_t* sl_ = Afl + abase + (size_t)(C) * 8192; \
    _Pragma("unroll") \
    for (int it_ = 0; it_ < 8; it_++) { \
        int w_ = (it_ * 256 + tid) * 4; \
        cp16(dst_ + ((uint32_t)w_ << 2), sh_ + w_); \
        cp16(dst_ + 32768u + ((uint32_t)w_ << 2), sl_ + w_); \
    } \
} while (0)
#define PF_BH(C) do { \
    uint32_t dst_ = smb + (32768u << 2); \
    const uint32_t* s_ = Bfh + (size_t)(C) * 8192; \
    _Pragma("unroll") \
    for (int it_ = 0; it_ < 8; it_++) { \
        int w_ = (it_ * 256 + tid) * 4; \
        cp16(dst_ + ((uint32_t)w_ << 2), s_ + w_); \
    } \
} while (0)
#define PF_BL(C) do { \
    uint32_t dst_ = smb + (40960u << 2); \
    const uint32_t* s_ = Bfl + (size_t)(C) * 8192; \
    _Pragma("unroll") \
    for (int it_ = 0; it_ < 8; it_++) { \
        int w_ = (it_ * 256 + tid) * 4; \
        cp16(dst_ + ((uint32_t)w_ << 2), s_ + w_); \
    } \
} while (0)

    PF_A(0); PF_BH(0);
    asm volatile("cp.async.commit_group;" ::: "memory");
    PF_BL(0);
    asm volatile("cp.async.commit_group;" ::: "memory");

#pragma unroll 1
    for (int c = 0; c < 6; c++) {
        const int ao = (c & 1) * 16384;
        // ---- even sub-phase: A(h,l) x Bh ----
        if (c < 5) asm volatile("cp.async.wait_group 1;" ::: "memory");
        else       asm volatile("cp.async.wait_group 0;" ::: "memory");
        __syncthreads();
#pragma unroll
        for (int ks = 0; ks < 8; ks++) {
            uint32_t bh[4][2];
#pragma unroll
            for (int nb = 0; nb < 4; nb++) {
                int nbg = wn * 4 + nb;
                uint2 h = *reinterpret_cast<uint2*>(&sm[32768 + ((nbg * 8 + ks) * 32 + lane) * 2]);
                bh[nb][0] = h.x; bh[nb][1] = h.y;
            }
#pragma unroll
            for (int mb = 0; mb < 4; mb++) {
                int mbg = wm * 4 + mb;
                uint4 a4 = *reinterpret_cast<uint4*>(&sm[ao + ((mbg * 8 + ks) * 32 + lane) * 4]);
                uint4 l4 = *reinterpret_cast<uint4*>(&sm[ao + 8192 + ((mbg * 8 + ks) * 32 + lane) * 4]);
                uint32_t ah[4] = {a4.x, a4.y, a4.z, a4.w};
                uint32_t al[4] = {l4.x, l4.y, l4.z, l4.w};
#pragma unroll
                for (int nb = 0; nb < 4; nb++) {
                    mma16816(acc[mb][nb], ah, bh[nb]);
                    mma16816(acc[mb][nb], al, bh[nb]);
                }
            }
        }
        __syncthreads();
        if (c < 5) {
            PF_A(c + 1); PF_BH(c + 1);
            asm volatile("cp.async.commit_group;" ::: "memory");
        }
        // ---- odd sub-phase: A(h) x Bl ----
        if (c < 5) asm volatile("cp.async.wait_group 1;" ::: "memory");
        else       asm volatile("cp.async.wait_group 0;" ::: "memory");
        __syncthreads();
#pragma unroll
        for (int ks = 0; ks < 8; ks++) {
            uint32_t bl[4][2];
#pragma unroll
            for (int nb = 0; nb < 4; nb++) {
                int nbg = wn * 4 + nb;
                uint2 l = *reinterpret_cast<uint2*>(&sm[40960 + ((nbg * 8 + ks) * 32 + lane) * 2]);
                bl[nb][0] = l.x; bl[nb][1] = l.y;
            }
#pragma unroll
            for (int mb = 0; mb < 4; mb++) {
                int mbg = wm * 4 + mb;
                uint4 a4 = *reinterpret_cast<uint4*>(&sm[ao + ((mbg * 8 + ks) * 32 + lane) * 4]);
                uint32_t ah[4] = {a4.x, a4.y, a4.z, a4.w};
#pragma unroll
                for (int nb = 0; nb < 4; nb++) mma16816(acc[mb][nb], ah, bl[nb]);
            }
        }
        __syncthreads();
        if (c < 5) {
            PF_BL(c + 1);
            asm volatile("cp.async.commit_group;" ::: "memory");
        }
    }
#undef PF_A
#undef PF_BH
#undef PF_BL

    // epilogue
    int g = lane >> 2, t = lane & 3;
#pragma unroll
    for (int mb = 0; mb < 4; mb++) {
#pragma unroll
        for (int nb = 0; nb < 4; nb++) {
            int col = (wn * 4 + nb) * 8 + 2 * t;
            float b0 = bias[col], b1 = bias[col + 1];
            int row0 = n0 + wm * 64 + mb * 16 + g;
            float c0 = acc[mb][nb][0] + b0, c1 = acc[mb][nb][1] + b1;
            float c2 = acc[mb][nb][2] + b0, c3 = acc[mb][nb][3] + b1;
            if (row0 < NN) *reinterpret_cast<float2*>(&Cout[(size_t)row0 * DD + col]) = make_float2(c0, c1);
            if (row0 + 8 < NN) *reinterpret_cast<float2*>(&Cout[(size_t)(row0 + 8) * DD + col]) = make_float2(c2, c3);
        }
    }
}

// ---------------- square K=128 GEMM (W_in / W_o1): A resident converted, B cp.async frag ----------------
__global__ __launch_bounds__(256)
void k_wide1(const float* __restrict__ A,
             const uint32_t* __restrict__ gBh, const uint32_t* __restrict__ gBl,
             const float* __restrict__ bias, float* __restrict__ Cout) {
    extern __shared__ uint32_t sm[];  // Ah 8192, Al 8192, Bh 8192, Bl 8192
    const int tid = threadIdx.x, lane = tid & 31, wid = tid >> 5;
    const int wm = wid >> 2, wn = wid & 3;
    const int n0 = blockIdx.x * 128;
    const uint32_t smb = smem_u32(sm);

    // prefetch B
#pragma unroll
    for (int it = 0; it < 8; it++) {
        int w = (it * 256 + tid) * 4;
        cp16(smb + ((16384u + (uint32_t)w) << 2), gBh + w);
        cp16(smb + ((24576u + (uint32_t)w) << 2), gBl + w);
    }
    asm volatile("cp.async.commit_group;" ::: "memory");

    // load + split-convert A
#pragma unroll
    for (int it = 0; it < 16; it++) {
        int idx = it * 256 + tid;
        int row = idx >> 5, c4 = (idx & 31) * 4;
        int grow = n0 + row;
        float4 v = make_float4(0.f, 0.f, 0.f, 0.f);
        if (grow < NN) v = *reinterpret_cast<const float4*>(&A[(size_t)grow * DD + c4]);
        frag_store(sm, row, c4, v);
    }
    asm volatile("cp.async.wait_group 0;" ::: "memory");
    __syncthreads();

    float acc[4][4][4];
#pragma unroll
    for (int i = 0; i < 4; i++)
#pragma unroll
        for (int j = 0; j < 4; j++)
#pragma unroll
            for (int q = 0; q < 4; q++) acc[i][j][q] = 0.f;

#pragma unroll
    for (int ks = 0; ks < 8; ks++) {
        uint32_t bh[4][2], bl[4][2];
#pragma unroll
        for (int nb = 0; nb < 4; nb++) {
            int nbg = wn * 4 + nb;
            uint2 h = *reinterpret_cast<uint2*>(&sm[16384 + ((nbg * 8 + ks) * 32 + lane) * 2]);
            uint2 l = *reinterpret_cast<uint2*>(&sm[24576 + ((nbg * 8 + ks) * 32 + lane) * 2]);
            bh[nb][0] = h.x; bh[nb][1] = h.y; bl[nb][0] = l.x; bl[nb][1] = l.y;
        }
#pragma unroll
        for (int mb = 0; mb < 4; mb++) {
            int mbg = wm * 4 + mb;
            uint4 a4 = *reinterpret_cast<uint4*>(&sm[((mbg * 8 + ks) * 32 + lane) * 4]);
            uint4 l4 = *reinterpret_cast<uint4*>(&sm[8192 + ((mbg * 8 + ks) * 32 + lane) * 4]);
            uint32_t ah[4] = {a4.x, a4.y, a4.z, a4.w};
            uint32_t al[4] = {l4.x, l4.y, l4.z, l4.w};
#pragma unroll
            for (int nb = 0; nb < 4; nb++) {
                mma16816(acc[mb][nb], ah, bh[nb]);
                mma16816(acc[mb][nb], ah, bl[nb]);
                mma16816(acc[mb][nb], al, bh[nb]);
            }
        }
    }
    int g = lane >> 2, t = lane & 3;
#pragma unroll
    for (int mb = 0; mb < 4; mb++) {
#pragma unroll
        for (int nb = 0; nb < 4; nb++) {
            int col = (wn * 4 + nb) * 8 + 2 * t;
            float b0 = bias[col], b1 = bias[col + 1];
            int row0 = n0 + wm * 64 + mb * 16 + g;
            float c0 = lrelu(acc[mb][nb][0] + b0), c1 = lrelu(acc[mb][nb][1] + b1);
            float c2 = lrelu(acc[mb][nb][2] + b0), c3 = lrelu(acc[mb][nb][3] + b1);
            if (row0 < NN) *reinterpret_cast<float2*>(&Cout[(size_t)row0 * DD + col]) = make_float2(c0, c1);
            if (row0 + 8 < NN) *reinterpret_cast<float2*>(&Cout[(size_t)(row0 + 8) * DD + col]) = make_float2(c2, c3);
        }
    }
}

// ---------------- encoder GEMM (BN=32, K=768), round-3 style ----------------
template <int BN, bool ACT>
__global__ __launch_bounds__(256, 1)
void k_mma(const float* __restrict__ A0, int lda0,
           const __nv_bfloat16* __restrict__ Bh, const __nv_bfloat16* __restrict__ Bl,
           int K, const float* __restrict__ bias, float* __restrict__ C, int ldc) {
    constexpr int A_WORDS = 2048;
    constexpr int B_WORDS = (BN / 8) * 2 * 32 * 2;
    constexpr int MBW = 1;
    constexpr int NBC = 1;
    extern __shared__ uint32_t sm[];
    const int tid = threadIdx.x, lane = tid & 31, wid = tid >> 5;
    const int wm = wid, wn = 0;
    const int n0 = blockIdx.x * 128;
    const int NC = K / 32;
    float acc[MBW][4][4];
#pragma unroll
    for (int i = 0; i < MBW; i++)
#pragma unroll
        for (int j = 0; j < 4; j++)
#pragma unroll
            for (int q = 0; q < 4; q++) acc[i][j][q] = 0.f;
    float4 av[4];
    uint4 bv[NBC];
#define GLOAD(I) do { \
    int k0 = (I) * 32; \
    _Pragma("unroll") \
    for (int it = 0; it < 4; it++) { \
        int idx = it * 256 + tid; int row = idx >> 3, c4 = (idx & 7) * 4; int grow = n0 + row; \
        av[it] = make_float4(0.f, 0.f, 0.f, 0.f); \
        if (grow < NN) av[it] = *reinterpret_cast<const float4*>(&A0[(size_t)grow * lda0 + k0 + c4]); \
    } \
    _Pragma("unroll") \
    for (int it = 0; it < NBC; it++) { \
        int idx = it * 256 + tid; int m = idx >= BN * 4; int idx2 = m ? idx - BN * 4 : idx; \
        int n = idx2 & (BN - 1); int kc = idx2 / BN; \
        const __nv_bfloat16* src = (m ? Bl : Bh) + (size_t)n * K + k0 + kc * 8; \
        bv[it] = *reinterpret_cast<const uint4*>(src); \
    } \
} while (0)
#define SSTORE(I) do { \
    int s_ = (I) & 1; \
    _Pragma("unroll") \
    for (int it = 0; it < 4; it++) { \
        int idx = it * 256 + tid; int row = idx >> 3, c4 = (idx & 7) * 4; \
        int mb = row >> 4, rm = row & 15, g = rm & 7, r1 = rm >> 3; \
        int ks = c4 >> 4, khalf = ((c4 & 15) >= 8) ? 1 : 0, r = r1 + 2 * khalf, t0 = (c4 >> 1) & 3; \
        float4 v = av[it]; \
        __nv_bfloat16 h0 = __float2bfloat16_rn(v.x), h1 = __float2bfloat16_rn(v.y); \
        __nv_bfloat16 h2 = __float2bfloat16_rn(v.z), h3 = __float2bfloat16_rn(v.w); \
        __nv_bfloat162 H01(h0, h1), H23(h2, h3); \
        __nv_bfloat162 L01 = __floats2bfloat162_rn(v.x - __bfloat162float(h0), v.y - __bfloat162float(h1)); \
        __nv_bfloat162 L23 = __floats2bfloat162_rn(v.z - __bfloat162float(h2), v.w - __bfloat162float(h3)); \
        int base = ((mb * 2 + ks) * 32) * 4 + r; \
        int ab0 = (s_ * 2 + 0) * A_WORDS + base, ab1 = (s_ * 2 + 1) * A_WORDS + base; \
        sm[ab0 + (g * 4 + t0) * 4]     = *reinterpret_cast<uint32_t*>(&H01); \
        sm[ab0 + (g * 4 + t0 + 1) * 4] = *reinterpret_cast<uint32_t*>(&H23); \
        sm[ab1 + (g * 4 + t0) * 4]     = *reinterpret_cast<uint32_t*>(&L01); \
        sm[ab1 + (g * 4 + t0 + 1) * 4] = *reinterpret_cast<uint32_t*>(&L23); \
    } \
    _Pragma("unroll") \
    for (int it = 0; it < NBC; it++) { \
        int idx = it * 256 + tid; int m = idx >= BN * 4; int idx2 = m ? idx - BN * 4 : idx; \
        int n = idx2 & (BN - 1); int kc = idx2 / BN; \
        int ks = kc >> 1, r = kc & 1, nb = n >> 3, g = n & 7; \
        int a0 = 8192 + (s_ * 2 + m) * B_WORDS + ((nb * 2 + ks) * 32 + g * 4) * 2 + r; \
        sm[a0 + 0] = bv[it].x; sm[a0 + 2] = bv[it].y; sm[a0 + 4] = bv[it].z; sm[a0 + 6] = bv[it].w; \
    } \
} while (0)
#define COMPUTE(I) do { \
    int s_ = (I) & 1; \
    _Pragma("unroll") \
    for (int ks = 0; ks < 2; ks++) { \
        uint32_t bhF[4][2], blF[4][2]; \
        _Pragma("unroll") \
        for (int nb = 0; nb < 4; nb++) { \
            int nb_g = wn * 4 + nb; \
            if (nb_g < BN / 8) { \
                uint2 h = *reinterpret_cast<uint2*>(&sm[8192 + (s_ * 2 + 0) * B_WORDS + ((nb_g * 2 + ks) * 32 + lane) * 2]); \
                uint2 l = *reinterpret_cast<uint2*>(&sm[8192 + (s_ * 2 + 1) * B_WORDS + ((nb_g * 2 + ks) * 32 + lane) * 2]); \
                bhF[nb][0] = h.x; bhF[nb][1] = h.y; blF[nb][0] = l.x; blF[nb][1] = l.y; \
            } \
        } \
        _Pragma("unroll") \
        for (int mb = 0; mb < MBW; mb++) { \
            int mb_g = wm * MBW + mb; \
            uint4 ah4 = *reinterpret_cast<uint4*>(&sm[(s_ * 2 + 0) * A_WORDS + ((mb_g * 2 + ks) * 32 + lane) * 4]); \
            uint4 al4 = *reinterpret_cast<uint4*>(&sm[(s_ * 2 + 1) * A_WORDS + ((mb_g * 2 + ks) * 32 + lane) * 4]); \
            uint32_t ah[4] = {ah4.x, ah4.y, ah4.z, ah4.w}; \
            uint32_t al[4] = {al4.x, al4.y, al4.z, al4.w}; \
            _Pragma("unroll") \
            for (int nb = 0; nb < 4; nb++) { \
                if (wn * 4 + nb < BN / 8) { \
                    mma16816(acc[mb][nb], ah, bhF[nb]); \
                    mma16816(acc[mb][nb], ah, blF[nb]); \
                    mma16816(acc[mb][nb], al, bhF[nb]); \
                } \
            } \
        } \
    } \
} while (0)
    GLOAD(0);
    SSTORE(0);
    __syncthreads();
    for (int i = 0; i < NC; i++) {
        if (i + 1 < NC) GLOAD(i + 1);
        COMPUTE(i);
        if (i + 1 < NC) SSTORE(i + 1);
        __syncthreads();
    }
    int g = lane >> 2, t = lane & 3;
#pragma unroll
    for (int mb = 0; mb < MBW; mb++) {
#pragma unroll
        for (int nb = 0; nb < 4; nb++) {
            if (wn * 4 + nb >= BN / 8) continue;
            int col = (wn * 4 + nb) * 8 + 2 * t;
            float b0 = bias[col], b1 = bias[col + 1];
            int row0 = n0 + wm * (MBW * 16) + mb * 16 + g;
            float c0 = acc[mb][nb][0] + b0, c1 = acc[mb][nb][1] + b1;
            float c2 = acc[mb][nb][2] + b0, c3 = acc[mb][nb][3] + b1;
            if (ACT) { c0 = lrelu(c0); c1 = lrelu(c1); c2 = lrelu(c2); c3 = lrelu(c3); }
            if (row0 < NN) *reinterpret_cast<float2*>(&C[(size_t)row0 * ldc + col]) = make_float2(c0, c1);
            if (row0 + 8 < NN) *reinterpret_cast<float2*>(&C[(size_t)(row0 + 8) * ldc + col]) = make_float2(c2, c3);
        }
    }
#undef GLOAD
#undef SSTORE
#undef COMPUTE
}

// ---------------- host launch ----------------
extern "C" void kernel_launch(void* const* d_in, const int* in_sizes, int n_in,
                              void* d_out, int out_size) {
    const float* des = (const float*)d_in[0];
    const float* tweet = (const float*)d_in[1];
    const float* np_ = (const float*)d_in[2];
    const float* cp = (const float*)d_in[3];
    const int* ei = (const int*)d_in[4];
    const int* et = (const int*)d_in[5];
    const float* W_des = (const float*)d_in[6];
    const float* b_des = (const float*)d_in[7];
    const float* W_tw = (const float*)d_in[8];
    const float* b_tw = (const float*)d_in[9];
    const float* W_np = (const float*)d_in[10];
    const float* b_np = (const float*)d_in[11];
    const float* W_cp = (const float*)d_in[12];
    const float* b_cp = (const float*)d_in[13];
    const float* W_in = (const float*)d_in[14];
    const float* b_in = (const float*)d_in[15];
    const float* rel_w = (const float*)d_in[16];
    const float* root_w = (const float*)d_in[17];
    const float* rgcn_b = (const float*)d_in[18];
    const float* W_o1 = (const float*)d_in[19];
    const float* b_o1 = (const float*)d_in[20];
    const float* W_o2 = (const float*)d_in[21];
    const float* b_o2 = (const float*)d_in[22];
    float* out = (float*)d_out;

    void *vx, *vy, *vbh, *vbl, *vfh, *vfl, *vbc, *vah, *val;
    cudaGetSymbolAddress(&vx, g_x);
    cudaGetSymbolAddress(&vy, g_y);
    cudaGetSymbolAddress(&vbh, g_Bh);
    cudaGetSymbolAddress(&vbl, g_Bl);
    cudaGetSymbolAddress(&vfh, g_Bfh);
    cudaGetSymbolAddress(&vfl, g_Bfl);
    cudaGetSymbolAddress(&vbc, g_bcnt);
    cudaGetSymbolAddress(&vah, g_Afh);
    cudaGetSymbolAddress(&val, g_Afl);
    float* px = (float*)vx;
    float* py = (float*)vy;
    __nv_bfloat16* pBh = (__nv_bfloat16*)vbh;
    __nv_bfloat16* pBl = (__nv_bfloat16*)vbl;
    uint32_t* pFh = (uint32_t*)vfh;
    uint32_t* pFl = (uint32_t*)vfl;
    uint32_t* pAh = (uint32_t*)vah;
    uint32_t* pAl = (uint32_t*)val;
    int* pbc = (int*)vbc;

    const int SMEM32 = (8192 + 4 * 512) * 4;
    const int SMEM_W1 = 32768 * 4;       // 128 KB
    const int SMEM_LG = 49152 * 4;       // 192 KB
    const int SMEM_AG = 16384 * 4;       // 64 KB
    cudaFuncSetAttribute(k_mma<32, true>, cudaFuncAttributeMaxDynamicSharedMemorySize, SMEM32);
    cudaFuncSetAttribute(k_wide1, cudaFuncAttributeMaxDynamicSharedMemorySize, SMEM_W1);
    cudaFuncSetAttribute(k_lgemm, cudaFuncAttributeMaxDynamicSharedMemorySize, SMEM_LG);
    cudaFuncSetAttribute(k_aggX, cudaFuncAttributeMaxDynamicSharedMemorySize, SMEM_AG);

    // preps
    k_prep<<<(32 * 768 + 255) / 256, 256>>>(W_des, 768, 32, pBh + OFF_DES, pBl + OFF_DES);
    k_prep<<<(32 * 768 + 255) / 256, 256>>>(W_tw, 768, 32, pBh + OFF_TW, pBl + OFF_TW);
    k_prep_fragB<<<192, 256>>>(rel_w, root_w, 6, pFh + FOFF_LAYER, pFl + FOFF_LAYER);
    k_prep_fragB<<<32, 256>>>(nullptr, W_in, 1, pFh + FOFF_IN, pFl + FOFF_IN);
    k_prep_fragB<<<32, 256>>>(nullptr, W_o1, 1, pFh + FOFF_O1, pFl + FOFF_O1);

    // encoders -> y
    k_mma<32, true><<<NTILE, 256, SMEM32>>>(des, 768, pBh + OFF_DES, pBl + OFF_DES, 768, b_des, py + 0, DD);
    k_mma<32, true><<<NTILE, 256, SMEM32>>>(tweet, 768, pBh + OFF_TW, pBl + OFF_TW, 768, b_tw, py + 32, DD);
    k_enc_small<<<(NN * 64 + 255) / 256, 256>>>(np_, cp, W_np, b_np, W_cp, b_cp, py);

    // CSR build
    k_zero_int<<<(NBKT + 255) / 256, 256>>>(pbc, NBKT);
    k_count<<<(EE + 255) / 256, 256>>>(ei, et);
    k_invert<<<(NBKT + 255) / 256, 256>>>();
    k_scan1<<<NSCB, SCAN_T>>>();
    k_scan2<<<1, 256>>>();
    k_scan3<<<(NBKT + 255) / 256, 256>>>();
    k_fill<<<(EE + 255) / 256, 256>>>(ei, et);

    // x = lrelu(y @ W_in + b_in)
    k_wide1<<<NTILE, 256, SMEM_W1>>>(py, pFh + FOFF_IN, pFl + FOFF_IN, b_in, px);

    // 4 RGCN layers: aggregate-first, then fragment GEMM
    float* cur = px;
    float* nxt = py;
    for (int l = 0; l < 4; l++) {
        k_aggX<<<dim3(NTILE, 6), 256, SMEM_AG>>>(cur, pAh, pAl);
        k_lgemm<<<NTILE, 256, SMEM_LG>>>(pAh, pAl, pFh + FOFF_LAYER, pFl + FOFF_LAYER, rgcn_b, nxt);
        float* t = cur; cur = nxt; nxt = t;
    }

    // head
    k_wide1<<<NTILE, 256, SMEM_W1>>>(cur, pFh + FOFF_O1, pFl + FOFF_O1, b_o1, nxt);
    k_head<<<(NN * 32 + 255) / 256, 256>>>(nxt, W_o2, b_o2, out);
}